// round 1
// baseline (speedup 1.0000x reference)
#include <cuda_runtime.h>
#include <cstdint>

// ---------------------------------------------------------------------------
// SevenSacredNeurons fused kernel (fp32, packed f32x2 FMA)
//
// Pipeline per row:
//   h  = phi( x[256] @ W_in^T[256,49] + b_in )            stage 1
//   c  = phi( h @ Wn_flat^T[49,49] + bn )                 stage 2
//   t  = phi( c @ W_int^T[49,21] + b_int )                stage 3
//   n  = LayerNorm(t; gamma, beta, eps=1e-5)
//   out= n @ W_out^T[21,4] + b_out                        stage 4
//
// phi(x) = sigmoid(x/PHI) * (x*PHI / (1+|x|))
//        = x*PHI / ((1+exp(-x/PHI)) * (1+|x|))   (single rcp)
// ---------------------------------------------------------------------------

#define PHI_F      1.6180339887498949f
#define INV_PHI_F  0.6180339887498949f

// ---- packed f32x2 helpers --------------------------------------------------
static __device__ __forceinline__ unsigned long long pk2(float v) {
    unsigned long long r;
    asm("mov.b64 %0, {%1, %1};" : "=l"(r) : "f"(v));
    return r;
}
static __device__ __forceinline__ void upk(unsigned long long v, float& lo, float& hi) {
    asm("mov.b64 {%0, %1}, %2;" : "=f"(lo), "=f"(hi) : "l"(v));
}
static __device__ __forceinline__ unsigned long long ffma2(unsigned long long a,
                                                           unsigned long long b,
                                                           unsigned long long c) {
    unsigned long long d;
    asm("fma.rn.f32x2 %0, %1, %2, %3;" : "=l"(d) : "l"(a), "l"(b), "l"(c));
    return d;
}

static __device__ __forceinline__ float phi_spiral(float x) {
    float e   = __expf(-x * INV_PHI_F);
    float den = (1.0f + e) * (1.0f + fabsf(x));
    return x * PHI_F * __fdividef(1.0f, den);
}

// ---- shared memory layout (in floats) -------------------------------------
// Ws1  : [256][56]  stage1 weights transposed, j padded 49->56
// XH   : [64][256]  x chunk (transposed, swizzled)  /  later H [56][256]
// CS   : [56][256]  combined (stage2 out, transposed, swizzled)
// WN2  : [49][56]   stage2 weights transposed, padded
// WINT : [21][52]   stage3 weights row-major, i padded 49->52
static constexpr int OFF_WS1  = 0;          // 14336
static constexpr int OFF_XH   = 14336;      // 16384
static constexpr int OFF_CS   = 30720;      // 14336
static constexpr int OFF_WN2  = 45056;      // 2744
static constexpr int OFF_WINT = 47800;      // 1092
static constexpr int OFF_BIN  = 48892;      // 56
static constexpr int OFF_BN   = 48948;      // 56
static constexpr int OFF_BINT = 49004;      // 21
static constexpr int OFF_GAM  = 49025;      // 21
static constexpr int OFF_BET  = 49046;      // 21
static constexpr int OFF_WOUT = 49067;      // 84
static constexpr int OFF_BOUT = 49151;      // 4
static constexpr int SMEM_FLOATS = 49155;
static constexpr int SMEM_BYTES  = SMEM_FLOATS * 4;   // 196620 B < 227 KB

// ---- GEMM microkernel: 4 rows x 14 cols (7 j-pairs) per thread -------------
// sW  : [K][56] weights, row i at sW + i*56 ; thread covers cols 14*cg..+13
// sX4 : [K][64] float4 rows; float4 g holds rows 4g..4g+3 at swizzled slot
template <int K>
static __device__ __forceinline__ void gemm_pairs(const float* __restrict__ sW,
                                                  const float4* __restrict__ sX4,
                                                  int rg, int cg,
                                                  unsigned long long acc[28]) {
    const float* wbase = sW + cg * 14;
    for (int i = 0; i < K; ++i) {
        int s = (i >> 3) & 7;
        float4 xv = sX4[i * 64 + (rg ^ s)];
        unsigned long long x0 = pk2(xv.x);
        unsigned long long x1 = pk2(xv.y);
        unsigned long long x2 = pk2(xv.z);
        unsigned long long x3 = pk2(xv.w);
        const float* wr = wbase + i * 56;
#pragma unroll
        for (int p = 0; p < 7; ++p) {
            unsigned long long w = *reinterpret_cast<const unsigned long long*>(wr + 2 * p);
            acc[p]      = ffma2(x0, w, acc[p]);
            acc[7 + p]  = ffma2(x1, w, acc[7 + p]);
            acc[14 + p] = ffma2(x2, w, acc[14 + p]);
            acc[21 + p] = ffma2(x3, w, acc[21 + p]);
        }
    }
}

// epilogue: +bias, phi, write transposed+swizzled [j][row] as float4 over rows
static __device__ __forceinline__ void epilogue_pairs(const unsigned long long acc[28],
                                                      const float* __restrict__ sBias,
                                                      float4* __restrict__ sDst4,
                                                      int rg, int cg) {
#pragma unroll
    for (int p = 0; p < 7; ++p) {
        int j0 = cg * 14 + 2 * p;
        float b0 = sBias[j0], b1 = sBias[j0 + 1];
        float l0, h0, l1, h1, l2, h2, l3, h3;
        upk(acc[p],      l0, h0);
        upk(acc[7 + p],  l1, h1);
        upk(acc[14 + p], l2, h2);
        upk(acc[21 + p], l3, h3);
        float4 v0 = make_float4(phi_spiral(l0 + b0), phi_spiral(l1 + b0),
                                phi_spiral(l2 + b0), phi_spiral(l3 + b0));
        float4 v1 = make_float4(phi_spiral(h0 + b1), phi_spiral(h1 + b1),
                                phi_spiral(h2 + b1), phi_spiral(h3 + b1));
        sDst4[j0 * 64 + (rg ^ ((j0 >> 3) & 7))] = v0;
        sDst4[(j0 + 1) * 64 + (rg ^ (((j0 + 1) >> 3) & 7))] = v1;
    }
}

__global__ __launch_bounds__(256, 1)
void sacred_kernel(const float* __restrict__ x,
                   const float* __restrict__ W_in,  const float* __restrict__ b_in,
                   const float* __restrict__ Wn,    const float* __restrict__ bn,
                   const float* __restrict__ W_int, const float* __restrict__ b_int,
                   const float* __restrict__ gamma, const float* __restrict__ beta,
                   const float* __restrict__ W_out, const float* __restrict__ b_out,
                   float* __restrict__ out) {
    extern __shared__ float sm[];
    const int tid = threadIdx.x;
    const int rg  = tid & 63;   // row group (4 rows each) 0..63
    const int cg  = tid >> 6;   // col group (14 cols each) 0..3
    const long long rowBase = (long long)blockIdx.x * 256;

    float*  sWS1  = sm + OFF_WS1;
    float*  sWN2  = sm + OFF_WN2;
    float*  sWINT = sm + OFF_WINT;
    float*  sBIN  = sm + OFF_BIN;
    float*  sBN   = sm + OFF_BN;
    float*  sBINT = sm + OFF_BINT;
    float*  sGAM  = sm + OFF_GAM;
    float*  sBET  = sm + OFF_BET;
    float*  sWOUT = sm + OFF_WOUT;
    float*  sBOUT = sm + OFF_BOUT;
    float*  XHf   = sm + OFF_XH;
    float4* XH4   = reinterpret_cast<float4*>(sm + OFF_XH);
    float4* CS4   = reinterpret_cast<float4*>(sm + OFF_CS);
    const float* CSf = sm + OFF_CS;

    // ---- weight staging: zero pads, then coalesced fill --------------------
    for (int k = tid; k < 14336; k += 256) sWS1[k] = 0.0f;
    for (int k = tid; k < 2744;  k += 256) sWN2[k] = 0.0f;
    for (int k = tid; k < 1092;  k += 256) sWINT[k] = 0.0f;
    if (tid < 56) { sBIN[tid] = 0.0f; sBN[tid] = 0.0f; }
    __syncthreads();

    for (int k = tid; k < 49 * 256; k += 256) {       // W_in[j][i] -> Ws1[i][j]
        int j = k >> 8, i = k & 255;
        sWS1[i * 56 + j] = W_in[k];
    }
    for (int k = tid; k < 49 * 49; k += 256) {        // Wn_flat[j][i] -> WN2[i][j]
        int j = k / 49, i = k - j * 49;
        sWN2[i * 56 + j] = Wn[k];
    }
    for (int k = tid; k < 21 * 49; k += 256) {        // W_int[j][i] -> WINT[j][i pad 52]
        int j = k / 49, i = k - j * 49;
        sWINT[j * 52 + i] = W_int[k];
    }
    if (tid < 49) { sBIN[tid] = b_in[tid]; sBN[tid] = bn[tid]; }
    if (tid < 21) { sBINT[tid] = b_int[tid]; sGAM[tid] = gamma[tid]; sBET[tid] = beta[tid]; }
    if (tid < 84) sWOUT[tid] = W_out[tid];
    if (tid < 4)  sBOUT[tid] = b_out[tid];
    // (no sync needed here; the sync after the first chunk store covers it)

    // ---- stage 1: [256 rows x 49] = x @ W_in^T, K=256 in 4 chunks of 64 ----
    unsigned long long acc[28];
#pragma unroll
    for (int q = 0; q < 28; ++q) acc[q] = 0ull;

    for (int c = 0; c < 4; ++c) {
        // coalesced global load, swizzled transposed store into XH[i][row]
#pragma unroll
        for (int it = 0; it < 16; ++it) {
            int f   = it * 256 + tid;        // float4 id within chunk
            int row = f >> 4;                // 0..255
            int i0  = (f & 15) << 2;         // 0..60
            float4 v = *reinterpret_cast<const float4*>(
                x + (rowBase + row) * 256 + c * 64 + i0);
            int rgS = row >> 2, rr = row & 3;
#pragma unroll
            for (int k = 0; k < 4; ++k) {
                int i = i0 + k;
                XHf[i * 256 + ((rgS ^ ((i >> 3) & 7)) << 2) + rr] = (&v.x)[k];
            }
        }
        __syncthreads();
        gemm_pairs<64>(sWS1 + c * 64 * 56, XH4, rg, cg, acc);
        __syncthreads();
    }
    // h = phi(acc + b_in), stored transposed into XH (x data now dead)
    epilogue_pairs(acc, sBIN, XH4, rg, cg);
    __syncthreads();

    // ---- stage 2: combined = phi(h @ Wn_flat^T + bn), K=49 -----------------
#pragma unroll
    for (int q = 0; q < 28; ++q) acc[q] = 0ull;
    gemm_pairs<49>(sWN2, XH4, rg, cg, acc);
    epilogue_pairs(acc, sBN, CS4, rg, cg);
    __syncthreads();

    // ---- stage 3 + LN + stage 4: one row per thread ------------------------
    {
        const int row = tid;
        const int rg3 = row >> 2, rr3 = row & 3;
        float cv[52];
#pragma unroll
        for (int i = 0; i < 49; ++i)
            cv[i] = CSf[i * 256 + ((rg3 ^ ((i >> 3) & 7)) << 2) + rr3];
        cv[49] = 0.0f; cv[50] = 0.0f; cv[51] = 0.0f;

        const float4* W4 = reinterpret_cast<const float4*>(sm + OFF_WINT);
        float integ[21];
#pragma unroll
        for (int j = 0; j < 21; ++j) {
            float a = sBINT[j];
#pragma unroll
            for (int q = 0; q < 13; ++q) {
                float4 w = W4[j * 13 + q];
                a = fmaf(cv[4 * q],     w.x, a);
                a = fmaf(cv[4 * q + 1], w.y, a);
                a = fmaf(cv[4 * q + 2], w.z, a);
                a = fmaf(cv[4 * q + 3], w.w, a);
            }
            integ[j] = phi_spiral(a);
        }

        float ssum = 0.0f;
#pragma unroll
        for (int j = 0; j < 21; ++j) ssum += integ[j];
        float mu = ssum * (1.0f / 21.0f);
        float vs = 0.0f;
#pragma unroll
        for (int j = 0; j < 21; ++j) { float d = integ[j] - mu; vs = fmaf(d, d, vs); }
        float rs = rsqrtf(vs * (1.0f / 21.0f) + 1e-5f);

        float o0 = sBOUT[0], o1 = sBOUT[1], o2 = sBOUT[2], o3 = sBOUT[3];
#pragma unroll
        for (int j = 0; j < 21; ++j) {
            float n = (integ[j] - mu) * rs;
            n = fmaf(n, sGAM[j], sBET[j]);
            o0 = fmaf(n, sWOUT[j],      o0);
            o1 = fmaf(n, sWOUT[21 + j], o1);
            o2 = fmaf(n, sWOUT[42 + j], o2);
            o3 = fmaf(n, sWOUT[63 + j], o3);
        }
        reinterpret_cast<float4*>(out)[rowBase + row] = make_float4(o0, o1, o2, o3);
    }
}

extern "C" void kernel_launch(void* const* d_in, const int* in_sizes, int n_in,
                              void* d_out, int out_size) {
    const float* x     = (const float*)d_in[0];
    const float* W_in  = (const float*)d_in[1];
    const float* b_in  = (const float*)d_in[2];
    const float* Wn    = (const float*)d_in[3];
    const float* bn    = (const float*)d_in[4];
    const float* W_int = (const float*)d_in[5];
    const float* b_int = (const float*)d_in[6];
    const float* gamma = (const float*)d_in[7];
    const float* beta  = (const float*)d_in[8];
    const float* W_out = (const float*)d_in[9];
    const float* b_out = (const float*)d_in[10];

    long long rows = (long long)in_sizes[0] / 256;   // 262144
    int grid = (int)(rows / 256);                    // 1024

    cudaFuncSetAttribute(sacred_kernel,
                         cudaFuncAttributeMaxDynamicSharedMemorySize, SMEM_BYTES);
    sacred_kernel<<<grid, 256, SMEM_BYTES>>>(x, W_in, b_in, Wn, bn, W_int, b_int,
                                             gamma, beta, W_out, b_out,
                                             (float*)d_out);
}